// round 12
// baseline (speedup 1.0000x reference)
#include <cuda_runtime.h>
#include <cuda_bf16.h>

#define N_NODES 50000
#define N_EDGES 800000
#define D_IN    96
#define D_EDGE  32
#define D_OUT   96
#define D_FEAT  128          // D_IN + D_EDGE, matches W's K dimension
#define N_TYPES 4

typedef unsigned long long ull;

#define PACKF2(dst, lo, hi) \
    asm("mov.b64 %0, {%1, %2};" : "=l"(dst) : "f"(lo), "f"(hi))
#define UNPACKF2(lo, hi, src) \
    asm("mov.b64 {%0, %1}, %2;" : "=f"(lo), "=f"(hi) : "l"(src))
// packed dual-FMA: acc.lo += a.lo*b.lo ; acc.hi += a.hi*b.hi
#define FFMA2(acc, a, b) \
    asm("fma.rn.f32x2 %0, %1, %2, %0;" : "+l"(acc) : "l"(a), "l"(b))
// 16B async copy global->shared
#define CPASYNC16(saddr, gptr) \
    asm volatile("cp.async.ca.shared.global [%0], [%1], 16;" \
                 :: "r"(saddr), "l"(gptr) : "memory")
#define CPASYNC_COMMIT() asm volatile("cp.async.commit_group;" ::: "memory")
#define CPASYNC_WAIT0()  asm volatile("cp.async.wait_group 0;" ::: "memory")

// feat[t][n][0:96]   = sum of x[src] over type-t edges into n
// feat[t][n][96:128] = sum of |ef[src]-ef[dst]| over those edges
// then cnt[t][n] (edge counts as float)
#define FEAT_ELEMS ((size_t)N_TYPES * N_NODES * D_FEAT)
#define CNT_OFFSET FEAT_ELEMS
__device__ __align__(16) float g_scratch[FEAT_ELEMS + (size_t)N_TYPES * N_NODES + 16];

// ---------------------------------------------------------------------------
// Kernel 1: edge scatter (scalar-atomic version, measured fastest).
// ---------------------------------------------------------------------------
#define SC_BATCH 4

__global__ __launch_bounds__(256) void scatter_kernel(
    const float* __restrict__ x,      // [N, 96]
    const float* __restrict__ ef,     // [N, 32]
    const int*   __restrict__ src,    // [E]
    const int*   __restrict__ dst,    // [E]
    const int*   __restrict__ et)     // [E]
{
    const int lane = threadIdx.x & 31;
    const int gw   = (blockIdx.x * blockDim.x + threadIdx.x) >> 5;
    const int nw   = (gridDim.x * blockDim.x) >> 5;

    float* cnt = g_scratch + CNT_OFFSET;

    for (long e0 = (long)gw * SC_BATCH; e0 < N_EDGES; e0 += (long)nw * SC_BATCH) {
        int  s[SC_BATCH], d[SC_BATCH], t[SC_BATCH];
        bool v[SC_BATCH];
#pragma unroll
        for (int i = 0; i < SC_BATCH; i++) {
            long e = e0 + i;
            v[i] = (e < N_EDGES);
            long ec = v[i] ? e : 0;
            s[i] = __ldg(&src[ec]);
            d[i] = __ldg(&dst[ec]);
            t[i] = __ldg(&et[ec]);
        }
#pragma unroll
        for (int i = 0; i < SC_BATCH; i++) {
            if (!v[i]) continue;
            const float* xr = x  + (size_t)s[i] * D_IN;
            float x0 = xr[lane], x1 = xr[lane + 32], x2 = xr[lane + 64];
            float ea = ef[(size_t)s[i] * D_EDGE + lane];
            float eb = ef[(size_t)d[i] * D_EDGE + lane];
            float ev = fabsf(ea - eb);

            float* row = g_scratch + ((size_t)t[i] * N_NODES + d[i]) * D_FEAT;
            atomicAdd(row + lane,      x0);
            atomicAdd(row + lane + 32, x1);
            atomicAdd(row + lane + 64, x2);
            atomicAdd(row + lane + 96, ev);
            if (lane == 0)
                atomicAdd(&cnt[(size_t)t[i] * N_NODES + d[i]], 1.0f);
        }
    }
}

// ---------------------------------------------------------------------------
// Kernel 2: out[n] = sum_t ( (0.25*feat[t][n]) @ W[t] + cnt[t][n]*0.25*b[t] ).
// 192 threads, TILE_N=96 (6 warps x 16 nodes = 8 packed pairs/warp).
// Per k-step per warp: 3 LDS.32 (W) + 4 LDS.128-bcast (xs) feed 48 FMAs ->
// smem crossbar load per node drops 30% vs 8-node warps.
// W double-buffered in cp.async chunks of 16 k-rows. smem 64 KB -> 3 CTAs/SM.
// ---------------------------------------------------------------------------
#define TILE_N    96
#define NPW       16                          // nodes per warp
#define XT_STRIDE 100                         // 400B rows: 16B-aligned
#define KCHUNK    16
#define NCHUNK    (D_FEAT / KCHUNK)           // 8
#define SM_XS   (D_FEAT * XT_STRIDE)          // 12800 floats
#define SM_WB   (2 * KCHUNK * D_OUT)          // 3072 floats
#define GEMM_SMEM_BYTES ((SM_XS + SM_WB + D_OUT + TILE_N + 8) * 4)
#define GEMM_THREADS 192

__global__ __launch_bounds__(GEMM_THREADS, 3) void gemm_kernel(
    const float* __restrict__ W,      // [4, 128, 96]
    const float* __restrict__ b,      // [4, 96]
    float*       __restrict__ out)    // [N, 96]
{
    extern __shared__ __align__(16) float smem[];
    float (*xs)[XT_STRIDE] = (float(*)[XT_STRIDE])smem;       // [128][100]
    float* wbuf = smem + SM_XS;                                // [2][16][96]
    float* bsm  = smem + SM_XS + SM_WB;                        // [96]
    float* csm  = bsm + D_OUT;                                 // [96]

    const int node0 = blockIdx.x * TILE_N;
    const int tid   = threadIdx.x;
    const int wid   = tid >> 5;
    const int lane  = tid & 31;
    const int i0    = wid * NPW;              // 16 nodes per warp = 8 pairs

    const unsigned wb_smem = (unsigned)__cvta_generic_to_shared(wbuf);
    const float* cnt = g_scratch + CNT_OFFSET;

    ull acc[8][3];
#pragma unroll
    for (int p = 0; p < 8; p++)
        acc[p][0] = acc[p][1] = acc[p][2] = 0ull;

    for (int t = 0; t < N_TYPES; t++) {
        __syncthreads();   // previous type's xs/wbuf/bsm reads complete

        const float* Wt = W + (size_t)t * D_FEAT * D_OUT;

        // prefetch W chunk 0 -> wbuf[0]  (384 x 16B)
#pragma unroll
        for (int q = 0; q < 2; q++) {
            int id = q * GEMM_THREADS + tid;
            if (id < KCHUNK * D_OUT / 4)
                CPASYNC16(wb_smem + id * 16, Wt + id * 4);
        }
        CPASYNC_COMMIT();

        // bias / counts
        if (tid < D_OUT)
            bsm[tid] = 0.25f * b[t * D_OUT + tid];
        if (tid >= D_OUT && tid < D_OUT + TILE_N) {
            int r = tid - D_OUT;
            int n = node0 + r;
            csm[r] = (n < N_NODES) ? cnt[(size_t)t * N_NODES + n] : 0.0f;
        }

        // transposed feat tile (0.25 folded), float2 gmem reads
        const float* ft = g_scratch + (size_t)t * N_NODES * D_FEAT;
        for (int i2 = tid; i2 < TILE_N * D_FEAT / 2; i2 += GEMM_THREADS) {
            int r  = i2 >> 6;                 // node within tile
            int kp = i2 & 63;                 // k pair
            int n  = node0 + r;
            float2 v = make_float2(0.0f, 0.0f);
            if (n < N_NODES)
                v = *reinterpret_cast<const float2*>(ft + (size_t)n * D_FEAT + 2 * kp);
            xs[2 * kp][r]     = 0.25f * v.x;
            xs[2 * kp + 1][r] = 0.25f * v.y;
        }

        CPASYNC_WAIT0();
        __syncthreads();

        // k-chunk loop: compute chunk j while chunk j+1 streams in
#pragma unroll 1
        for (int j = 0; j < NCHUNK; j++) {
            if (j < NCHUNK - 1) {
                const float* Wc = Wt + (j + 1) * KCHUNK * D_OUT;
                unsigned sb = wb_smem + ((j + 1) & 1) * (KCHUNK * D_OUT * 4);
#pragma unroll
                for (int q = 0; q < 2; q++) {
                    int id = q * GEMM_THREADS + tid;
                    if (id < KCHUNK * D_OUT / 4)
                        CPASYNC16(sb + id * 16, Wc + id * 4);
                }
                CPASYNC_COMMIT();
            }

            const float* wb = wbuf + (j & 1) * (KCHUNK * D_OUT);
#pragma unroll
            for (int kk = 0; kk < KCHUNK; kk++) {
                const int k = j * KCHUNK + kk;
                float w0 = wb[kk * D_OUT + lane];
                float w1 = wb[kk * D_OUT + lane + 32];
                float w2 = wb[kk * D_OUT + lane + 64];
                ull W0, W1, W2;
                PACKF2(W0, w0, w0); PACKF2(W1, w1, w1); PACKF2(W2, w2, w2);
#pragma unroll
                for (int h = 0; h < 4; h++) {
                    ulonglong2 xv = *reinterpret_cast<const ulonglong2*>(
                                        &xs[k][i0 + 4 * h]);
                    FFMA2(acc[2 * h][0],     xv.x, W0);
                    FFMA2(acc[2 * h][1],     xv.x, W1);
                    FFMA2(acc[2 * h][2],     xv.x, W2);
                    FFMA2(acc[2 * h + 1][0], xv.y, W0);
                    FFMA2(acc[2 * h + 1][1], xv.y, W1);
                    FFMA2(acc[2 * h + 1][2], xv.y, W2);
                }
            }

            if (j < NCHUNK - 1) {
                CPASYNC_WAIT0();        // chunk j+1 landed
                __syncthreads();        // nobody still reads buf (j+1)&1
            }
        }

        // bias: acc[p][c] += pack(cnt_lo, cnt_hi) * pack(0.25 b_c, 0.25 b_c)
        float bb0 = bsm[lane], bb1 = bsm[lane + 32], bb2 = bsm[lane + 64];
        ull B0, B1, B2;
        PACKF2(B0, bb0, bb0); PACKF2(B1, bb1, bb1); PACKF2(B2, bb2, bb2);
#pragma unroll
        for (int p = 0; p < 8; p++) {
            ull CN;
            PACKF2(CN, csm[i0 + 2 * p], csm[i0 + 2 * p + 1]);
            FFMA2(acc[p][0], CN, B0);
            FFMA2(acc[p][1], CN, B1);
            FFMA2(acc[p][2], CN, B2);
        }
    }

#pragma unroll
    for (int p = 0; p < 8; p++) {
        int n_lo = node0 + i0 + 2 * p;
        int n_hi = n_lo + 1;
        float* o_lo = out + (size_t)n_lo * D_OUT;
        float* o_hi = out + (size_t)n_hi * D_OUT;
#pragma unroll
        for (int c = 0; c < 3; c++) {
            float lo, hi;
            UNPACKF2(lo, hi, acc[p][c]);
            if (n_lo < N_NODES) o_lo[lane + 32 * c] = lo;
            if (n_hi < N_NODES) o_hi[lane + 32 * c] = hi;
        }
    }
}

// ---------------------------------------------------------------------------
extern "C" void kernel_launch(void* const* d_in, const int* in_sizes, int n_in,
                              void* d_out, int out_size)
{
    const float* x   = (const float*)d_in[0];          // [N, 96]
    const float* ef  = (const float*)d_in[1];          // [N, 32]
    const int*   ei  = (const int*)  d_in[2];          // [2, E]
    const int*   et  = (const int*)  d_in[3];          // [E]
    const float* W   = (const float*)d_in[4];          // [4, 128, 96]
    const float* b   = (const float*)d_in[5];          // [4, 96]
    float*       out = (float*)d_out;                  // [N, 96]

    const int* srcp = ei;
    const int* dstp = ei + N_EDGES;

    // zero the aggregation scratch (feat + cnt)
    void* scratch_ptr = nullptr;
    cudaGetSymbolAddress(&scratch_ptr, g_scratch);
    cudaMemsetAsync(scratch_ptr, 0, sizeof(g_scratch), 0);

    scatter_kernel<<<592, 256>>>(x, ef, srcp, dstp, et);

    static int smem_set = 0;
    if (!smem_set) {
        cudaFuncSetAttribute(gemm_kernel,
                             cudaFuncAttributeMaxDynamicSharedMemorySize,
                             GEMM_SMEM_BYTES);
        smem_set = 1;
    }
    gemm_kernel<<<(N_NODES + TILE_N - 1) / TILE_N, GEMM_THREADS,
                  GEMM_SMEM_BYTES>>>(W, b, out);
}